// round 15
// baseline (speedup 1.0000x reference)
#include <cuda_runtime.h>
#include <cuda_fp16.h>
#include <mma.h>
#include <math.h>

using namespace nvcuda;

#define BB 32
#define LL 52
#define VV 10000
#define HH 512
#define ENCK 401408
#define TT 51
#define G4 2048
#define KSPLIT 128
#define KCHUNK 3136    /* 128 * 3136 = 401408 exact */
#define MROWS 1664
#define PLD 72

__device__ int   g_sort[BB];
__device__ int   g_declen[BB];
__device__ int   g_caps[BB*LL];
__device__ int   g_prow[TT*BB];
__device__ int   g_mact;
__device__ float g_part[(long long)KSPLIT*BB*HH];
__device__ float g_x0bn[BB*HH];
__device__ float g_xw[(long long)LL*BB*G4];
__device__ float g_hbuf[2][BB*HH];
__device__ unsigned g_bar;
__device__ __half g_wih_h[(long long)G4*HH];
__device__ __half g_fcw_h[(long long)VV*HH];
__device__ __half g_a4h[(long long)MROWS*HH];
__device__ __half g_h2h[(long long)TT*BB*HH];

// ---------------- TMA 1D bulk + mbarrier helpers ----------------
__device__ __forceinline__ unsigned smaddr(const void* p) {
    return (unsigned)__cvta_generic_to_shared(p);
}
__device__ __forceinline__ void mbinit(unsigned mbar, unsigned cnt) {
    asm volatile("mbarrier.init.shared.b64 [%0], %1;" :: "r"(mbar), "r"(cnt) : "memory");
}
__device__ __forceinline__ void mexpect(unsigned mbar, unsigned bytes) {
    asm volatile("mbarrier.arrive.expect_tx.shared.b64 _, [%0], %1;"
                 :: "r"(mbar), "r"(bytes) : "memory");
}
__device__ __forceinline__ void mwait(unsigned mbar, unsigned parity) {
    asm volatile(
        "{\n\t.reg .pred P;\n\t"
        "LW%=:\n\t"
        "mbarrier.try_wait.parity.acquire.cta.shared::cta.b64 P, [%0], %1, 0x989680;\n\t"
        "@P bra LD%=;\n\t"
        "bra LW%=;\n\t"
        "LD%=:\n\t}"
        :: "r"(mbar), "r"(parity) : "memory");
}
__device__ __forceinline__ void bulkcp(unsigned dst, const void* src, unsigned bytes, unsigned mbar) {
    asm volatile(
        "cp.async.bulk.shared::cluster.global.mbarrier::complete_tx::bytes [%0], [%1], %2, [%3];"
        :: "r"(dst), "l"(src), "r"(bytes), "r"(mbar) : "memory");
}

__global__ void k0_setup(const int* __restrict__ caps, const int* __restrict__ lens,
                         float* __restrict__ out, long long out_size) {
    __shared__ int cnt[TT], off[TT+1];
    int t = threadIdx.x;
    if (t == 0) {
        g_bar = 0u;
        int len[BB]; bool used[BB];
        for (int i = 0; i < BB; i++) { len[i] = lens[i]; used[i] = false; }
        for (int r = 0; r < BB; r++) {
            int best = -1;
            for (int i = 0; i < BB; i++)
                if (!used[i] && (best < 0 || len[i] > len[best])) best = i;
            used[best] = true; g_sort[r] = best; g_declen[r] = len[best] - 1;
        }
    }
    __syncthreads();
    if (t < TT) {
        int c = 0;
        for (int b = 0; b < BB; b++) if (g_declen[b] > t) c++;
        cnt[t] = c;
    }
    __syncthreads();
    if (t == 0) {
        int s = 0;
        for (int i = 0; i < TT; i++) { off[i] = s; s += cnt[i]; }
        off[TT] = s; g_mact = s;
    }
    __syncthreads();
    for (int i = t; i < TT*BB; i += blockDim.x) {
        int tt = i >> 5, bb = i & 31;
        if (g_declen[bb] > tt) g_prow[off[tt] + bb] = i;
    }
    long long P = (long long)BB * TT * VV;
    for (int i = t; i < BB*LL; i += blockDim.x) {
        int b = i / LL, c = i % LL;
        int v = caps[g_sort[b]*LL + c];
        g_caps[i] = v;
        if (P + i < out_size) out[P + i] = (float)v;
    }
    for (int i = t; i < BB; i += blockDim.x) {
        if (P + BB*LL + i      < out_size) out[P + BB*LL + i]      = (float)g_declen[i];
        if (P + BB*LL + BB + i < out_size) out[P + BB*LL + BB + i] = (float)g_sort[i];
    }
}

// zero-fill inactive prediction rows. (also keeps k1 at ncu profile slot 3)
__global__ void kzero(float* __restrict__ out, long long out_size) {
    int bid = blockIdx.x;
    int tt = bid >> 5, bb = bid & 31;
    if (g_declen[bb] > tt) return;
    long long base = (long long)bb * TT * VV + (long long)tt * VV;
    for (int i = threadIdx.x; i < VV; i += blockDim.x) {
        long long idx = base + i;
        if (idx < out_size) out[idx] = 0.f;
    }
}

// convert wih + fcw to half (grid-stride)
__global__ void kc_w(const float* __restrict__ wih, const float* __restrict__ fcw) {
    const long long NW = (long long)G4 * HH;
    const long long NF = (long long)VV * HH;
    long long i = (long long)blockIdx.x * blockDim.x + threadIdx.x;
    long long stride = (long long)gridDim.x * blockDim.x;
    for (; i < NW + NF; i += stride) {
        if (i < NW) g_wih_h[i] = __float2half(wih[i]);
        else        g_fcw_h[i - NW] = __float2half(fcw[i - NW]);
    }
}

// build A-half for k4
__global__ void kc_a4(const float* __restrict__ embw) {
    int r = blockIdx.x, t = threadIdx.x;
    const float* src;
    if (r < BB) src = g_x0bn + r * HH;
    else { int rr = r - BB; src = embw + (long long)g_caps[(rr & 31)*LL + (rr >> 5)] * HH; }
    __half* dst = g_a4h + (long long)r * HH;
    for (int i = t; i < HH; i += blockDim.x) dst[i] = __float2half(src[i]);
}

// ---- k1: x0 partials (tf32). Tile 32m x 256n, K-split 128, stage K=32 (128B rows).
// smem 2 x 41.5KB = 83KB -> 2 blocks/SM resident (was 1). grid (2,128).
__global__ __launch_bounds__(256) void k1_initgemm(const float* __restrict__ enc,
                                                   const float* __restrict__ w) {
    extern __shared__ float sm[];
    __shared__ unsigned long long mb[2];
    int t = threadIdx.x;
    int wid = t >> 5;
    int n0 = blockIdx.x * 256;
    long long kbase = (long long)blockIdx.y * KCHUNK;
    unsigned mbar[2] = { smaddr(&mb[0]), smaddr(&mb[1]) };
    if (t == 0) { mbinit(mbar[0], 1); mbinit(mbar[1], 1); }
    __syncthreads();

    const int STAGES = KCHUNK / 32;         // 98
    const unsigned STB = 288u * 128u;       // 36864 B/stage
    const int SST = 288 * 36;               // stage stride in floats

    const float* bsrc = w + (long long)(n0 + t) * ENCK + kbase;
    int bdrow = (32 + t) * 36;
    const float* asrc = (t < 32) ? enc + (long long)g_sort[t] * ENCK + kbase : 0;
    int adrow = t * 36;

    wmma::fragment<wmma::accumulator,16,16,8,float> acc[2][2];
#pragma unroll
    for (int mi = 0; mi < 2; mi++)
#pragma unroll
        for (int nj = 0; nj < 2; nj++) wmma::fill_fragment(acc[mi][nj], 0.f);

    if (t == 0) mexpect(mbar[0], STB);
    __syncthreads();
    bulkcp(smaddr(sm + bdrow), bsrc, 128, mbar[0]);
    if (t < 32) bulkcp(smaddr(sm + adrow), asrc, 128, mbar[0]);
    if (t == 0) mexpect(mbar[1], STB);
    __syncthreads();
    bulkcp(smaddr(sm + SST + bdrow), bsrc + 32, 128, mbar[1]);
    if (t < 32) bulkcp(smaddr(sm + SST + adrow), asrc + 32, 128, mbar[1]);

    for (int s = 0; s < STAGES; s++) {
        int c = s & 1;
        mwait(mbar[c], (unsigned)((s >> 1) & 1));
        float* As = sm + c * SST;
        float* Bs = As + 32 * 36;
#pragma unroll
        for (int ks = 0; ks < 4; ks++) {
            wmma::fragment<wmma::matrix_a,16,16,8,wmma::precision::tf32,wmma::row_major> af[2];
            wmma::fragment<wmma::matrix_b,16,16,8,wmma::precision::tf32,wmma::col_major> bf[2];
#pragma unroll
            for (int mi = 0; mi < 2; mi++) {
                wmma::load_matrix_sync(af[mi], &As[(mi*16)*36 + ks*8], 36);
#pragma unroll
                for (int e = 0; e < af[mi].num_elements; e++)
                    af[mi].x[e] = wmma::__float_to_tf32(af[mi].x[e]);
            }
#pragma unroll
            for (int nj = 0; nj < 2; nj++) {
                wmma::load_matrix_sync(bf[nj], &Bs[(wid*32 + nj*16)*36 + ks*8], 36);
#pragma unroll
                for (int e = 0; e < bf[nj].num_elements; e++)
                    bf[nj].x[e] = wmma::__float_to_tf32(bf[nj].x[e]);
            }
#pragma unroll
            for (int mi = 0; mi < 2; mi++)
#pragma unroll
                for (int nj = 0; nj < 2; nj++)
                    wmma::mma_sync(acc[mi][nj], af[mi], bf[nj], acc[mi][nj]);
        }
        __syncthreads();
        if (s + 2 < STAGES) {
            if (t == 0) mexpect(mbar[c], STB);
            __syncthreads();
            bulkcp(smaddr(sm + c*SST + bdrow), bsrc + (long long)(s+2)*32, 128, mbar[c]);
            if (t < 32) bulkcp(smaddr(sm + c*SST + adrow), asrc + (long long)(s+2)*32, 128, mbar[c]);
        }
    }
    float* base = g_part + (long long)blockIdx.y * BB * HH;
#pragma unroll
    for (int mi = 0; mi < 2; mi++)
#pragma unroll
        for (int nj = 0; nj < 2; nj++)
            wmma::store_matrix_sync(base + mi*16*HH + n0 + wid*32 + nj*16,
                                    acc[mi][nj], HH, wmma::mem_row_major);
}

__global__ void k2_bn(const float* __restrict__ bias, const float* __restrict__ gamma,
                      const float* __restrict__ beta) {
    int n = blockIdx.x, t = threadIdx.x;
    int b = t & 31, grp = t >> 5;
    float s = 0.f;
    for (int ks = grp; ks < KSPLIT; ks += 4)
        s += g_part[((long long)ks * BB + b) * HH + n];
    __shared__ float red[128];
    red[t] = s; __syncthreads();
    if (t < 32) {
        float x = red[t] + red[t+32] + red[t+64] + red[t+96] + bias[n];
        float sum = x, sq = x * x;
#pragma unroll
        for (int o = 16; o > 0; o >>= 1) {
            sum += __shfl_xor_sync(0xffffffffu, sum, o);
            sq  += __shfl_xor_sync(0xffffffffu, sq,  o);
        }
        float mu = sum * (1.f/32.f);
        float var = sq * (1.f/32.f) - mu * mu;
        g_x0bn[b * HH + n] = (x - mu) * rsqrtf(var + 1e-5f) * gamma[n] + beta[n];
    }
}

// ---- fp16 bulk-TMA GEMM body: tile 128m x 256n, K=512, stage K=128 halves.
template<typename EPI>
__device__ __forceinline__ void bulk_gemm_h(const __half* arow0, const __half* brow0,
                                            __half* smh, EPI epi) {
    __shared__ unsigned long long mb[2];
    int t = threadIdx.x;
    int wid = t >> 5, wm = wid >> 2, wn = wid & 3;
    unsigned mbar[2] = { smaddr(&mb[0]), smaddr(&mb[1]) };
    if (t == 0) { mbinit(mbar[0], 1); mbinit(mbar[1], 1); }
    __syncthreads();

    const int STAGES = HH / 128;            // 4
    const unsigned STB = 384u * 256u;
    const int SST = 384 * 136;
    int adrow = t * 136;
    int bdrow = (128 + t) * 136;

    wmma::fragment<wmma::accumulator,16,16,16,float> acc[4][4];
#pragma unroll
    for (int mi = 0; mi < 4; mi++)
#pragma unroll
        for (int nj = 0; nj < 4; nj++) wmma::fill_fragment(acc[mi][nj], 0.f);

    if (t == 0) mexpect(mbar[0], STB);
    __syncthreads();
    bulkcp(smaddr(smh + bdrow), brow0, 256, mbar[0]);
    if (t < 128) bulkcp(smaddr(smh + adrow), arow0, 256, mbar[0]);
    if (t == 0) mexpect(mbar[1], STB);
    __syncthreads();
    bulkcp(smaddr(smh + SST + bdrow), brow0 + 128, 256, mbar[1]);
    if (t < 128) bulkcp(smaddr(smh + SST + adrow), arow0 + 128, 256, mbar[1]);

    for (int s = 0; s < STAGES; s++) {
        int c = s & 1;
        mwait(mbar[c], (unsigned)((s >> 1) & 1));
        __half* As = smh + c * SST;
        __half* Bs = As + 128 * 136;
#pragma unroll
        for (int ks = 0; ks < 8; ks++) {
            wmma::fragment<wmma::matrix_a,16,16,16,__half,wmma::row_major> af[4];
            wmma::fragment<wmma::matrix_b,16,16,16,__half,wmma::col_major> bf[4];
#pragma unroll
            for (int mi = 0; mi < 4; mi++)
                wmma::load_matrix_sync(af[mi], &As[(wm*64 + mi*16)*136 + ks*16], 136);
#pragma unroll
            for (int nj = 0; nj < 4; nj++)
                wmma::load_matrix_sync(bf[nj], &Bs[(wn*64 + nj*16)*136 + ks*16], 136);
#pragma unroll
            for (int mi = 0; mi < 4; mi++)
#pragma unroll
                for (int nj = 0; nj < 4; nj++)
                    wmma::mma_sync(acc[mi][nj], af[mi], bf[nj], acc[mi][nj]);
        }
        __syncthreads();
        if (s + 2 < STAGES) {
            if (t == 0) mexpect(mbar[c], STB);
            __syncthreads();
            bulkcp(smaddr(smh + c*SST + bdrow), brow0 + (s+2)*128, 256, mbar[c]);
            if (t < 128) bulkcp(smaddr(smh + c*SST + adrow), arow0 + (s+2)*128, 256, mbar[c]);
        }
    }
    float* sC = (float*)smh;
#pragma unroll
    for (int mi = 0; mi < 4; mi++)
#pragma unroll
        for (int nj = 0; nj < 4; nj++)
            wmma::store_matrix_sync(&sC[(wm*64 + mi*16)*260 + wn*64 + nj*16],
                                    acc[mi][nj], 260, wmma::mem_row_major);
    __syncthreads();
    epi(sC);
}

// ---- k4: XW = A4h(1664x512) @ wih_h.T + bias. grid (13, 8).
__global__ __launch_bounds__(256) void k4_xw(const float* __restrict__ bih,
                                             const float* __restrict__ bhh) {
    extern __shared__ __half sm4[];
    int t = threadIdx.x;
    int m0 = blockIdx.x * 128, n0 = blockIdx.y * 256;
    const __half* arow0 = (t < 128) ? g_a4h + (long long)(m0 + t) * HH : 0;
    const __half* brow0 = g_wih_h + (long long)(n0 + t) * HH;
    bulk_gemm_h(arow0, brow0, sm4, [&](float* sC) {
#pragma unroll
        for (int j = 0; j < 128; j++) {
            int e = t + j*256;
            int row = e >> 8, cl = e & 255;
            int col = n0 + cl;
            g_xw[(long long)(m0 + row) * G4 + col] = sC[row*260 + cl] + bih[col] + bhh[col];
        }
    });
}

// ---- k5: persistent LSTM via fp16 wmma. 32 blocks x 128 thr.
__global__ __launch_bounds__(128) void k5_all(const float* __restrict__ whh) {
    extern __shared__ __half smh5[];
    __half* Bs = smh5;                      // [64][520]
    __half* Ah = smh5 + 64*520;             // [32][520]
    float*  sP = (float*)(smh5 + 96*520);   // [4][32][PLD]
    int t = threadIdx.x;
    int w = t >> 5;
    int c0 = blockIdx.x * 16;

    {   // convert whh slice to fp16 smem once
        int r = t >> 1, g = r >> 4, j = r & 15;
        const float* wp = whh + (long long)(g*512 + c0 + j) * HH + (t & 1) * 256;
        __half* dst = Bs + r*520 + (t & 1) * 256;
#pragma unroll 8
        for (int i = 0; i < 64; i++) {
            float4 v = *(const float4*)(wp + i*4);
            *(__half2*)(dst + i*4)     = __floats2half2_rn(v.x, v.y);
            *(__half2*)(dst + i*4 + 2) = __floats2half2_rn(v.z, v.w);
        }
    }
    {
        unsigned* az = (unsigned*)Ah;
        for (int i = t; i < 32*520/2; i += 128) az[i] = 0u;
    }

    int eb = t & 31;
    float c_reg[4] = {0.f,0.f,0.f,0.f}, h_reg[4] = {0.f,0.f,0.f,0.f};
    int dl = g_declen[eb];
    int hb = t >> 2, hq = (t & 3) * 128;

    for (int cell = 0; cell < LL; cell++) {
        if (cell > 0) {
            const float* hp = g_hbuf[cell & 1] + hb * HH + hq;
            __half* dst = Ah + hb*520 + hq;
#pragma unroll 8
            for (int i = 0; i < 32; i++) {
                float4 v = __ldcg((const float4*)(hp + i*4));
                *(__half2*)(dst + i*4)     = __floats2half2_rn(v.x, v.y);
                *(__half2*)(dst + i*4 + 2) = __floats2half2_rn(v.z, v.w);
            }
        }
        __syncthreads();
        {
            wmma::fragment<wmma::accumulator,16,16,16,float> acc[2][4];
#pragma unroll
            for (int mi = 0; mi < 2; mi++)
#pragma unroll
                for (int nj = 0; nj < 4; nj++) wmma::fill_fragment(acc[mi][nj], 0.f);
            int kw = w * 128;
#pragma unroll
            for (int ks = 0; ks < 8; ks++) {
                wmma::fragment<wmma::matrix_a,16,16,16,__half,wmma::row_major> af[2];
                wmma::fragment<wmma::matrix_b,16,16,16,__half,wmma::col_major> bf[4];
#pragma unroll
                for (int mi = 0; mi < 2; mi++)
                    wmma::load_matrix_sync(af[mi], &Ah[(mi*16)*520 + kw + ks*16], 520);
#pragma unroll
                for (int nj = 0; nj < 4; nj++)
                    wmma::load_matrix_sync(bf[nj], &Bs[(nj*16)*520 + kw + ks*16], 520);
#pragma unroll
                for (int mi = 0; mi < 2; mi++)
#pragma unroll
                    for (int nj = 0; nj < 4; nj++)
                        wmma::mma_sync(acc[mi][nj], af[mi], bf[nj], acc[mi][nj]);
            }
            float* sPw = sP + w * 32 * PLD;
#pragma unroll
            for (int mi = 0; mi < 2; mi++)
#pragma unroll
                for (int nj = 0; nj < 4; nj++)
                    wmma::store_matrix_sync(&sPw[(mi*16)*PLD + nj*16],
                                            acc[mi][nj], PLD, wmma::mem_row_major);
        }
        __syncthreads();
        {
            const float* xw = g_xw + ((long long)cell * BB + eb) * G4;
#pragma unroll
            for (int jj = 0; jj < 4; jj++) {
                int j = w * 4 + jj;
                int col = c0 + j;
                float gv4[4];
#pragma unroll
                for (int g = 0; g < 4; g++) {
                    int n = g * 16 + j;
                    float s = sP[0*32*PLD + eb*PLD + n] + sP[1*32*PLD + eb*PLD + n]
                            + sP[2*32*PLD + eb*PLD + n] + sP[3*32*PLD + eb*PLD + n];
                    gv4[g] = s + xw[g*512 + col];
                }
                float si = 1.f/(1.f+expf(-gv4[0])), sf = 1.f/(1.f+expf(-gv4[1]));
                float tg = tanhf(gv4[2]),           so = 1.f/(1.f+expf(-gv4[3]));
                float cn = sf * c_reg[jj] + si * tg;
                float hn = so * tanhf(cn);
                bool act = (cell == 0) || (dl > (cell - 1));
                c_reg[jj] = act ? cn : c_reg[jj];
                h_reg[jj] = act ? hn : h_reg[jj];
                g_hbuf[(cell + 1) & 1][eb * HH + col] = h_reg[jj];
                if (cell >= 1)
                    g_h2h[((long long)(cell - 1) * BB + eb) * HH + col] = __float2half(hn);
            }
        }
        __syncthreads();
        if (cell + 1 < LL) {
            if (t == 0) {
                __threadfence();
                atomicAdd(&g_bar, 1u);
                unsigned tgt = (unsigned)(cell + 1) * gridDim.x;
                while (*(volatile unsigned*)&g_bar < tgt) __nanosleep(64);
            }
            __syncthreads();
        }
    }
}

// ---- k6: packed-M predictions. grid (13, 40); blocks beyond g_mact exit.
__global__ __launch_bounds__(256) void k6_fc(const float* __restrict__ fcb,
                                             float* __restrict__ out, long long out_size) {
    extern __shared__ __half sm6[];
    int t = threadIdx.x;
    int m0 = blockIdx.x * 128, n0 = blockIdx.y * 256;
    int Mact = g_mact;
    if (m0 >= Mact) return;
    const __half* arow0 = 0;
    if (t < 128) {
        int p = m0 + t;
        if (p >= Mact) p = 0;
        arow0 = g_h2h + (long long)g_prow[p] * HH;
    }
    int bn = n0 + t; if (bn >= VV) bn = VV - 1;
    const __half* brow0 = g_fcw_h + (long long)bn * HH;
    bulk_gemm_h(arow0, brow0, sm6, [&](float* sC) {
#pragma unroll
        for (int j = 0; j < 128; j++) {
            int e = t + j*256;
            int row = e >> 8, cl = e & 255;
            int p = m0 + row;
            if (p >= Mact) continue;
            int col = n0 + cl;
            if (col >= VV) continue;
            int rr = g_prow[p];
            int tt = rr >> 5, bb = rr & 31;
            long long idx = (long long)bb * TT * VV + (long long)tt * VV + col;
            if (idx < out_size)
                out[idx] = sC[row*260 + cl] + fcb[col];
        }
    });
}

extern "C" void kernel_launch(void* const* d_in, const int* in_sizes, int n_in,
                              void* d_out, int out_size) {
    const float* enc   = (const float*)d_in[0];
    const int*   caps  = (const int*)  d_in[1];
    const int*   lens  = (const int*)  d_in[2];
    const float* embw  = (const float*)d_in[3];
    const float* initw = (const float*)d_in[4];
    const float* initb = (const float*)d_in[5];
    const float* gamma = (const float*)d_in[6];
    const float* beta  = (const float*)d_in[7];
    const float* wih   = (const float*)d_in[8];
    const float* whh   = (const float*)d_in[9];
    const float* bih   = (const float*)d_in[10];
    const float* bhh   = (const float*)d_in[11];
    const float* fcw   = (const float*)d_in[12];
    const float* fcb   = (const float*)d_in[13];
    float* out = (float*)d_out;
    long long osz = (long long)out_size;

    const int SM1  = 2 * 288 * 36 * 4;          // 82,944 B -> 2 blocks/SM
    const int SMGH = 2 * 384 * 136 * 2;         // 208,896 B
    const int SM5  = 96*520*2 + 4*32*PLD*4;     // 136,704 B
    cudaFuncSetAttribute(k1_initgemm, cudaFuncAttributeMaxDynamicSharedMemorySize, SM1);
    cudaFuncSetAttribute(k4_xw,       cudaFuncAttributeMaxDynamicSharedMemorySize, SMGH);
    cudaFuncSetAttribute(k6_fc,       cudaFuncAttributeMaxDynamicSharedMemorySize, SMGH);
    cudaFuncSetAttribute(k5_all,      cudaFuncAttributeMaxDynamicSharedMemorySize, SM5);

    k0_setup<<<1, 256>>>(caps, lens, out, osz);
    kzero<<<TT*BB, 256>>>(out, osz);
    kc_w<<<592, 256>>>(wih, fcw);
    k1_initgemm<<<dim3(2, KSPLIT), 256, SM1>>>(enc, initw);   // profile slot 3
    k2_bn<<<512, 128>>>(initb, gamma, beta);
    kc_a4<<<MROWS, 128>>>(embw);
    k4_xw<<<dim3(13, 8), 256, SMGH>>>(bih, bhh);
    k5_all<<<32, 128, SM5>>>(whh);
    k6_fc<<<dim3(13, 40), 256, SMGH>>>(fcb, out, osz);
}

// round 16
// speedup vs baseline: 1.0528x; 1.0528x over previous
#include <cuda_runtime.h>
#include <cuda_fp16.h>
#include <mma.h>
#include <math.h>

using namespace nvcuda;

#define BB 32
#define LL 52
#define VV 10000
#define HH 512
#define ENCK 401408
#define TT 51
#define G4 2048
#define KSPLIT 32
#define KCHUNK 12544   /* 32 * 12544 = 401408 exact */
#define MROWS 1664
#define PLD 72

__device__ int   g_sort[BB];
__device__ int   g_declen[BB];
__device__ int   g_caps[BB*LL];
__device__ int   g_prow[TT*BB];
__device__ int   g_mact;
__device__ float g_part[(long long)KSPLIT*BB*HH];
__device__ float g_x0bn[BB*HH];
__device__ float g_xw[(long long)LL*BB*G4];
__device__ float g_hbuf[2][BB*HH];
__device__ unsigned g_bar;
__device__ __half g_wih_h[(long long)G4*HH];
__device__ __half g_fcw_h[(long long)VV*HH];
__device__ __half g_a4h[(long long)MROWS*HH];
__device__ __half g_h2h[(long long)TT*BB*HH];

// ---------------- TMA 1D bulk + mbarrier helpers ----------------
__device__ __forceinline__ unsigned smaddr(const void* p) {
    return (unsigned)__cvta_generic_to_shared(p);
}
__device__ __forceinline__ void mbinit(unsigned mbar, unsigned cnt) {
    asm volatile("mbarrier.init.shared.b64 [%0], %1;" :: "r"(mbar), "r"(cnt) : "memory");
}
__device__ __forceinline__ void mexpect(unsigned mbar, unsigned bytes) {
    asm volatile("mbarrier.arrive.expect_tx.shared.b64 _, [%0], %1;"
                 :: "r"(mbar), "r"(bytes) : "memory");
}
__device__ __forceinline__ void mwait(unsigned mbar, unsigned parity) {
    asm volatile(
        "{\n\t.reg .pred P;\n\t"
        "LW%=:\n\t"
        "mbarrier.try_wait.parity.acquire.cta.shared::cta.b64 P, [%0], %1, 0x989680;\n\t"
        "@P bra LD%=;\n\t"
        "bra LW%=;\n\t"
        "LD%=:\n\t}"
        :: "r"(mbar), "r"(parity) : "memory");
}
__device__ __forceinline__ void bulkcp(unsigned dst, const void* src, unsigned bytes, unsigned mbar) {
    asm volatile(
        "cp.async.bulk.shared::cluster.global.mbarrier::complete_tx::bytes [%0], [%1], %2, [%3];"
        :: "r"(dst), "l"(src), "r"(bytes), "r"(mbar) : "memory");
}

__global__ void k0_setup(const int* __restrict__ caps, const int* __restrict__ lens,
                         float* __restrict__ out, long long out_size) {
    __shared__ int cnt[TT], off[TT+1];
    int t = threadIdx.x;
    if (t == 0) {
        g_bar = 0u;
        int len[BB]; bool used[BB];
        for (int i = 0; i < BB; i++) { len[i] = lens[i]; used[i] = false; }
        for (int r = 0; r < BB; r++) {
            int best = -1;
            for (int i = 0; i < BB; i++)
                if (!used[i] && (best < 0 || len[i] > len[best])) best = i;
            used[best] = true; g_sort[r] = best; g_declen[r] = len[best] - 1;
        }
    }
    __syncthreads();
    if (t < TT) {
        int c = 0;
        for (int b = 0; b < BB; b++) if (g_declen[b] > t) c++;
        cnt[t] = c;
    }
    __syncthreads();
    if (t == 0) {
        int s = 0;
        for (int i = 0; i < TT; i++) { off[i] = s; s += cnt[i]; }
        off[TT] = s; g_mact = s;
    }
    __syncthreads();
    for (int i = t; i < TT*BB; i += blockDim.x) {
        int tt = i >> 5, bb = i & 31;
        if (g_declen[bb] > tt) g_prow[off[tt] + bb] = i;
    }
    long long P = (long long)BB * TT * VV;
    for (int i = t; i < BB*LL; i += blockDim.x) {
        int b = i / LL, c = i % LL;
        int v = caps[g_sort[b]*LL + c];
        g_caps[i] = v;
        if (P + i < out_size) out[P + i] = (float)v;
    }
    for (int i = t; i < BB; i += blockDim.x) {
        if (P + BB*LL + i      < out_size) out[P + BB*LL + i]      = (float)g_declen[i];
        if (P + BB*LL + BB + i < out_size) out[P + BB*LL + BB + i] = (float)g_sort[i];
    }
}

// zero-fill inactive prediction rows (also keeps k1 at ncu profile slot 3)
__global__ void kzero(float* __restrict__ out, long long out_size) {
    int bid = blockIdx.x;
    int tt = bid >> 5, bb = bid & 31;
    if (g_declen[bb] > tt) return;
    long long base = (long long)bb * TT * VV + (long long)tt * VV;
    for (int i = threadIdx.x; i < VV; i += blockDim.x) {
        long long idx = base + i;
        if (idx < out_size) out[idx] = 0.f;
    }
}

// convert wih + fcw to half (grid-stride)
__global__ void kc_w(const float* __restrict__ wih, const float* __restrict__ fcw) {
    const long long NW = (long long)G4 * HH;
    const long long NF = (long long)VV * HH;
    long long i = (long long)blockIdx.x * blockDim.x + threadIdx.x;
    long long stride = (long long)gridDim.x * blockDim.x;
    for (; i < NW + NF; i += stride) {
        if (i < NW) g_wih_h[i] = __float2half(wih[i]);
        else        g_fcw_h[i - NW] = __float2half(fcw[i - NW]);
    }
}

// build A-half for k4
__global__ void kc_a4(const float* __restrict__ embw) {
    int r = blockIdx.x, t = threadIdx.x;
    const float* src;
    if (r < BB) src = g_x0bn + r * HH;
    else { int rr = r - BB; src = embw + (long long)g_caps[(rr & 31)*LL + (rr >> 5)] * HH; }
    __half* dst = g_a4h + (long long)r * HH;
    for (int i = t; i < HH; i += blockDim.x) dst[i] = __float2half(src[i]);
}

// ---- k1: x0 partials (tf32). Tile 32m x 64n, K-split 32, stage K=256 (1KB requests).
// grid (8, 32) = 256 blocks; 8 warps = 4 n-warps x 2 k-half warps; smem 2 x 99.8KB.
__global__ __launch_bounds__(256) void k1_initgemm(const float* __restrict__ enc,
                                                   const float* __restrict__ w) {
    extern __shared__ float sm[];
    __shared__ unsigned long long mb[2];
    int t = threadIdx.x;
    int wid = t >> 5, wk = wid >> 2, wn = wid & 3;
    int n0 = blockIdx.x * 64;
    long long kbase = (long long)blockIdx.y * KCHUNK;
    unsigned mbar[2] = { smaddr(&mb[0]), smaddr(&mb[1]) };
    if (t == 0) { mbinit(mbar[0], 1); mbinit(mbar[1], 1); }
    __syncthreads();

    const int STAGES = KCHUNK / 256;        // 49
    const unsigned STB = 96u * 1024u;       // 98304 B/stage
    const int SST = 96 * 260;               // stage stride in floats

    // copy role: t<32 -> enc row t (dst rows 0..31); t in [32,96) -> w row n0+t-32
    const float* src0 = 0;
    int drow = 0;
    if (t < 32)      { src0 = enc + (long long)g_sort[t] * ENCK + kbase;        drow = t * 260; }
    else if (t < 96) { src0 = w + (long long)(n0 + t - 32) * ENCK + kbase;      drow = t * 260; }

    wmma::fragment<wmma::accumulator,16,16,8,float> acc[2];
    wmma::fill_fragment(acc[0], 0.f);
    wmma::fill_fragment(acc[1], 0.f);

    if (t == 0) mexpect(mbar[0], STB);
    __syncthreads();
    if (t < 96) bulkcp(smaddr(sm + drow), src0, 1024, mbar[0]);
    if (t == 0) mexpect(mbar[1], STB);
    __syncthreads();
    if (t < 96) bulkcp(smaddr(sm + SST + drow), src0 + 256, 1024, mbar[1]);

    for (int s = 0; s < STAGES; s++) {
        int c = s & 1;
        mwait(mbar[c], (unsigned)((s >> 1) & 1));
        float* As = sm + c * SST;
        float* Bs = As + 32 * 260;
        int kofs = wk * 128;
#pragma unroll
        for (int ks = 0; ks < 16; ks++) {
            wmma::fragment<wmma::matrix_a,16,16,8,wmma::precision::tf32,wmma::row_major> af[2];
            wmma::fragment<wmma::matrix_b,16,16,8,wmma::precision::tf32,wmma::col_major> bf;
#pragma unroll
            for (int mi = 0; mi < 2; mi++) {
                wmma::load_matrix_sync(af[mi], &As[(mi*16)*260 + kofs + ks*8], 260);
#pragma unroll
                for (int e = 0; e < af[mi].num_elements; e++)
                    af[mi].x[e] = wmma::__float_to_tf32(af[mi].x[e]);
            }
            wmma::load_matrix_sync(bf, &Bs[(wn*16)*260 + kofs + ks*8], 260);
#pragma unroll
            for (int e = 0; e < bf.num_elements; e++)
                bf.x[e] = wmma::__float_to_tf32(bf.x[e]);
            wmma::mma_sync(acc[0], af[0], bf, acc[0]);
            wmma::mma_sync(acc[1], af[1], bf, acc[1]);
        }
        __syncthreads();
        if (s + 2 < STAGES) {
            if (t == 0) mexpect(mbar[c], STB);
            __syncthreads();
            if (t < 96) bulkcp(smaddr(sm + c*SST + drow), src0 + (long long)(s+2)*256, 1024, mbar[c]);
        }
    }
    // reduce k-half partials through smem (ld 68, multiple of 4)
    float* sP = sm;    // reuse stage 0: [wk][32][68]
#pragma unroll
    for (int mi = 0; mi < 2; mi++)
        wmma::store_matrix_sync(&sP[wk*2176 + (mi*16)*68 + wn*16], acc[mi], 68, wmma::mem_row_major);
    __syncthreads();
    float* base = g_part + (long long)blockIdx.y * BB * HH;
#pragma unroll
    for (int i = 0; i < 8; i++) {
        int idx = t + i*256;
        int row = idx >> 6, col = idx & 63;
        base[row*HH + n0 + col] = sP[row*68 + col] + sP[2176 + row*68 + col];
    }
}

__global__ void k2_bn(const float* __restrict__ bias, const float* __restrict__ gamma,
                      const float* __restrict__ beta) {
    int n = blockIdx.x, t = threadIdx.x;
    int b = t & 31, grp = t >> 5;
    float s = 0.f;
    for (int ks = grp; ks < KSPLIT; ks += 4)
        s += g_part[((long long)ks * BB + b) * HH + n];
    __shared__ float red[128];
    red[t] = s; __syncthreads();
    if (t < 32) {
        float x = red[t] + red[t+32] + red[t+64] + red[t+96] + bias[n];
        float sum = x, sq = x * x;
#pragma unroll
        for (int o = 16; o > 0; o >>= 1) {
            sum += __shfl_xor_sync(0xffffffffu, sum, o);
            sq  += __shfl_xor_sync(0xffffffffu, sq,  o);
        }
        float mu = sum * (1.f/32.f);
        float var = sq * (1.f/32.f) - mu * mu;
        g_x0bn[b * HH + n] = (x - mu) * rsqrtf(var + 1e-5f) * gamma[n] + beta[n];
    }
}

// ---- fp16 bulk-TMA GEMM body: tile 128m x 256n, K=512, stage K=128 halves.
template<typename EPI>
__device__ __forceinline__ void bulk_gemm_h(const __half* arow0, const __half* brow0,
                                            __half* smh, EPI epi) {
    __shared__ unsigned long long mb[2];
    int t = threadIdx.x;
    int wid = t >> 5, wm = wid >> 2, wn = wid & 3;
    unsigned mbar[2] = { smaddr(&mb[0]), smaddr(&mb[1]) };
    if (t == 0) { mbinit(mbar[0], 1); mbinit(mbar[1], 1); }
    __syncthreads();

    const int STAGES = HH / 128;            // 4
    const unsigned STB = 384u * 256u;
    const int SST = 384 * 136;
    int adrow = t * 136;
    int bdrow = (128 + t) * 136;

    wmma::fragment<wmma::accumulator,16,16,16,float> acc[4][4];
#pragma unroll
    for (int mi = 0; mi < 4; mi++)
#pragma unroll
        for (int nj = 0; nj < 4; nj++) wmma::fill_fragment(acc[mi][nj], 0.f);

    if (t == 0) mexpect(mbar[0], STB);
    __syncthreads();
    bulkcp(smaddr(smh + bdrow), brow0, 256, mbar[0]);
    if (t < 128) bulkcp(smaddr(smh + adrow), arow0, 256, mbar[0]);
    if (t == 0) mexpect(mbar[1], STB);
    __syncthreads();
    bulkcp(smaddr(smh + SST + bdrow), brow0 + 128, 256, mbar[1]);
    if (t < 128) bulkcp(smaddr(smh + SST + adrow), arow0 + 128, 256, mbar[1]);

    for (int s = 0; s < STAGES; s++) {
        int c = s & 1;
        mwait(mbar[c], (unsigned)((s >> 1) & 1));
        __half* As = smh + c * SST;
        __half* Bs = As + 128 * 136;
#pragma unroll
        for (int ks = 0; ks < 8; ks++) {
            wmma::fragment<wmma::matrix_a,16,16,16,__half,wmma::row_major> af[4];
            wmma::fragment<wmma::matrix_b,16,16,16,__half,wmma::col_major> bf[4];
#pragma unroll
            for (int mi = 0; mi < 4; mi++)
                wmma::load_matrix_sync(af[mi], &As[(wm*64 + mi*16)*136 + ks*16], 136);
#pragma unroll
            for (int nj = 0; nj < 4; nj++)
                wmma::load_matrix_sync(bf[nj], &Bs[(wn*64 + nj*16)*136 + ks*16], 136);
#pragma unroll
            for (int mi = 0; mi < 4; mi++)
#pragma unroll
                for (int nj = 0; nj < 4; nj++)
                    wmma::mma_sync(acc[mi][nj], af[mi], bf[nj], acc[mi][nj]);
        }
        __syncthreads();
        if (s + 2 < STAGES) {
            if (t == 0) mexpect(mbar[c], STB);
            __syncthreads();
            bulkcp(smaddr(smh + c*SST + bdrow), brow0 + (s+2)*128, 256, mbar[c]);
            if (t < 128) bulkcp(smaddr(smh + c*SST + adrow), arow0 + (s+2)*128, 256, mbar[c]);
        }
    }
    float* sC = (float*)smh;
#pragma unroll
    for (int mi = 0; mi < 4; mi++)
#pragma unroll
        for (int nj = 0; nj < 4; nj++)
            wmma::store_matrix_sync(&sC[(wm*64 + mi*16)*260 + wn*64 + nj*16],
                                    acc[mi][nj], 260, wmma::mem_row_major);
    __syncthreads();
    epi(sC);
}

// ---- k4: XW = A4h(1664x512) @ wih_h.T + bias. grid (13, 8).
__global__ __launch_bounds__(256) void k4_xw(const float* __restrict__ bih,
                                             const float* __restrict__ bhh) {
    extern __shared__ __half sm4[];
    int t = threadIdx.x;
    int m0 = blockIdx.x * 128, n0 = blockIdx.y * 256;
    const __half* arow0 = (t < 128) ? g_a4h + (long long)(m0 + t) * HH : 0;
    const __half* brow0 = g_wih_h + (long long)(n0 + t) * HH;
    bulk_gemm_h(arow0, brow0, sm4, [&](float* sC) {
#pragma unroll
        for (int j = 0; j < 128; j++) {
            int e = t + j*256;
            int row = e >> 8, cl = e & 255;
            int col = n0 + cl;
            g_xw[(long long)(m0 + row) * G4 + col] = sC[row*260 + cl] + bih[col] + bhh[col];
        }
    });
}

// ---- k5: persistent LSTM via fp16 wmma. 32 blocks x 128 thr.
__global__ __launch_bounds__(128) void k5_all(const float* __restrict__ whh) {
    extern __shared__ __half smh5[];
    __half* Bs = smh5;                      // [64][520]
    __half* Ah = smh5 + 64*520;             // [32][520]
    float*  sP = (float*)(smh5 + 96*520);   // [4][32][PLD]
    int t = threadIdx.x;
    int w = t >> 5;
    int c0 = blockIdx.x * 16;

    {   // convert whh slice to fp16 smem once
        int r = t >> 1, g = r >> 4, j = r & 15;
        const float* wp = whh + (long long)(g*512 + c0 + j) * HH + (t & 1) * 256;
        __half* dst = Bs + r*520 + (t & 1) * 256;
#pragma unroll 8
        for (int i = 0; i < 64; i++) {
            float4 v = *(const float4*)(wp + i*4);
            *(__half2*)(dst + i*4)     = __floats2half2_rn(v.x, v.y);
            *(__half2*)(dst + i*4 + 2) = __floats2half2_rn(v.z, v.w);
        }
    }
    {
        unsigned* az = (unsigned*)Ah;
        for (int i = t; i < 32*520/2; i += 128) az[i] = 0u;
    }

    int eb = t & 31;
    float c_reg[4] = {0.f,0.f,0.f,0.f}, h_reg[4] = {0.f,0.f,0.f,0.f};
    int dl = g_declen[eb];
    int hb = t >> 2, hq = (t & 3) * 128;

    for (int cell = 0; cell < LL; cell++) {
        if (cell > 0) {
            const float* hp = g_hbuf[cell & 1] + hb * HH + hq;
            __half* dst = Ah + hb*520 + hq;
#pragma unroll 8
            for (int i = 0; i < 32; i++) {
                float4 v = __ldcg((const float4*)(hp + i*4));
                *(__half2*)(dst + i*4)     = __floats2half2_rn(v.x, v.y);
                *(__half2*)(dst + i*4 + 2) = __floats2half2_rn(v.z, v.w);
            }
        }
        __syncthreads();
        {
            wmma::fragment<wmma::accumulator,16,16,16,float> acc[2][4];
#pragma unroll
            for (int mi = 0; mi < 2; mi++)
#pragma unroll
                for (int nj = 0; nj < 4; nj++) wmma::fill_fragment(acc[mi][nj], 0.f);
            int kw = w * 128;
#pragma unroll
            for (int ks = 0; ks < 8; ks++) {
                wmma::fragment<wmma::matrix_a,16,16,16,__half,wmma::row_major> af[2];
                wmma::fragment<wmma::matrix_b,16,16,16,__half,wmma::col_major> bf[4];
#pragma unroll
                for (int mi = 0; mi < 2; mi++)
                    wmma::load_matrix_sync(af[mi], &Ah[(mi*16)*520 + kw + ks*16], 520);
#pragma unroll
                for (int nj = 0; nj < 4; nj++)
                    wmma::load_matrix_sync(bf[nj], &Bs[(nj*16)*520 + kw + ks*16], 520);
#pragma unroll
                for (int mi = 0; mi < 2; mi++)
#pragma unroll
                    for (int nj = 0; nj < 4; nj++)
                        wmma::mma_sync(acc[mi][nj], af[mi], bf[nj], acc[mi][nj]);
            }
            float* sPw = sP + w * 32 * PLD;
#pragma unroll
            for (int mi = 0; mi < 2; mi++)
#pragma unroll
                for (int nj = 0; nj < 4; nj++)
                    wmma::store_matrix_sync(&sPw[(mi*16)*PLD + nj*16],
                                            acc[mi][nj], PLD, wmma::mem_row_major);
        }
        __syncthreads();
        {
            const float* xw = g_xw + ((long long)cell * BB + eb) * G4;
#pragma unroll
            for (int jj = 0; jj < 4; jj++) {
                int j = w * 4 + jj;
                int col = c0 + j;
                float gv4[4];
#pragma unroll
                for (int g = 0; g < 4; g++) {
                    int n = g * 16 + j;
                    float s = sP[0*32*PLD + eb*PLD + n] + sP[1*32*PLD + eb*PLD + n]
                            + sP[2*32*PLD + eb*PLD + n] + sP[3*32*PLD + eb*PLD + n];
                    gv4[g] = s + xw[g*512 + col];
                }
                float si = 1.f/(1.f+expf(-gv4[0])), sf = 1.f/(1.f+expf(-gv4[1]));
                float tg = tanhf(gv4[2]),           so = 1.f/(1.f+expf(-gv4[3]));
                float cn = sf * c_reg[jj] + si * tg;
                float hn = so * tanhf(cn);
                bool act = (cell == 0) || (dl > (cell - 1));
                c_reg[jj] = act ? cn : c_reg[jj];
                h_reg[jj] = act ? hn : h_reg[jj];
                g_hbuf[(cell + 1) & 1][eb * HH + col] = h_reg[jj];
                if (cell >= 1)
                    g_h2h[((long long)(cell - 1) * BB + eb) * HH + col] = __float2half(hn);
            }
        }
        __syncthreads();
        if (cell + 1 < LL) {
            if (t == 0) {
                __threadfence();
                atomicAdd(&g_bar, 1u);
                unsigned tgt = (unsigned)(cell + 1) * gridDim.x;
                while (*(volatile unsigned*)&g_bar < tgt) __nanosleep(64);
            }
            __syncthreads();
        }
    }
}

// ---- k6: packed-M predictions. grid (13, 40); blocks beyond g_mact exit.
__global__ __launch_bounds__(256) void k6_fc(const float* __restrict__ fcb,
                                             float* __restrict__ out, long long out_size) {
    extern __shared__ __half sm6[];
    int t = threadIdx.x;
    int m0 = blockIdx.x * 128, n0 = blockIdx.y * 256;
    int Mact = g_mact;
    if (m0 >= Mact) return;
    const __half* arow0 = 0;
    if (t < 128) {
        int p = m0 + t;
        if (p >= Mact) p = 0;
        arow0 = g_h2h + (long long)g_prow[p] * HH;
    }
    int bn = n0 + t; if (bn >= VV) bn = VV - 1;
    const __half* brow0 = g_fcw_h + (long long)bn * HH;
    bulk_gemm_h(arow0, brow0, sm6, [&](float* sC) {
#pragma unroll
        for (int j = 0; j < 128; j++) {
            int e = t + j*256;
            int row = e >> 8, cl = e & 255;
            int p = m0 + row;
            if (p >= Mact) continue;
            int col = n0 + cl;
            if (col >= VV) continue;
            int rr = g_prow[p];
            int tt = rr >> 5, bb = rr & 31;
            long long idx = (long long)bb * TT * VV + (long long)tt * VV + col;
            if (idx < out_size)
                out[idx] = sC[row*260 + cl] + fcb[col];
        }
    });
}

extern "C" void kernel_launch(void* const* d_in, const int* in_sizes, int n_in,
                              void* d_out, int out_size) {
    const float* enc   = (const float*)d_in[0];
    const int*   caps  = (const int*)  d_in[1];
    const int*   lens  = (const int*)  d_in[2];
    const float* embw  = (const float*)d_in[3];
    const float* initw = (const float*)d_in[4];
    const float* initb = (const float*)d_in[5];
    const float* gamma = (const float*)d_in[6];
    const float* beta  = (const float*)d_in[7];
    const float* wih   = (const float*)d_in[8];
    const float* whh   = (const float*)d_in[9];
    const float* bih   = (const float*)d_in[10];
    const float* bhh   = (const float*)d_in[11];
    const float* fcw   = (const float*)d_in[12];
    const float* fcb   = (const float*)d_in[13];
    float* out = (float*)d_out;
    long long osz = (long long)out_size;

    const int SM1  = 2 * 96 * 260 * 4;          // 199,680 B
    const int SMGH = 2 * 384 * 136 * 2;         // 208,896 B
    const int SM5  = 96*520*2 + 4*32*PLD*4;     // 136,704 B
    cudaFuncSetAttribute(k1_initgemm, cudaFuncAttributeMaxDynamicSharedMemorySize, SM1);
    cudaFuncSetAttribute(k4_xw,       cudaFuncAttributeMaxDynamicSharedMemorySize, SMGH);
    cudaFuncSetAttribute(k6_fc,       cudaFuncAttributeMaxDynamicSharedMemorySize, SMGH);
    cudaFuncSetAttribute(k5_all,      cudaFuncAttributeMaxDynamicSharedMemorySize, SM5);

    k0_setup<<<1, 256>>>(caps, lens, out, osz);
    kzero<<<TT*BB, 256>>>(out, osz);
    kc_w<<<592, 256>>>(wih, fcw);
    k1_initgemm<<<dim3(8, KSPLIT), 256, SM1>>>(enc, initw);   // profile slot 3
    k2_bn<<<512, 128>>>(initb, gamma, beta);
    kc_a4<<<MROWS, 128>>>(embw);
    k4_xw<<<dim3(13, 8), 256, SMGH>>>(bih, bhh);
    k5_all<<<32, 128, SM5>>>(whh);
    k6_fc<<<dim3(13, 40), 256, SMGH>>>(fcb, out, osz);
}

// round 17
// speedup vs baseline: 1.1389x; 1.0818x over previous
#include <cuda_runtime.h>
#include <cuda_fp16.h>
#include <mma.h>
#include <math.h>

using namespace nvcuda;

#define BB 32
#define LL 52
#define VV 10000
#define HH 512
#define ENCK 401408
#define TT 51
#define G4 2048
#define KSPLIT 32
#define KCHUNK 12544   /* 32 * 12544 = 401408 exact */
#define MROWS 1664
#define PLD 72

__device__ int   g_sort[BB];
__device__ int   g_declen[BB];
__device__ int   g_caps[BB*LL];
__device__ int   g_prow[TT*BB];
__device__ int   g_mact;
__device__ float g_part[(long long)KSPLIT*BB*HH];
__device__ float g_x0bn[BB*HH];
__device__ float g_xw[(long long)LL*BB*G4];
__device__ float g_hbuf[2][BB*HH];
__device__ unsigned g_bar;
__device__ __half g_wih_h[(long long)G4*HH];
__device__ __half g_fcw_h[(long long)VV*HH];
__device__ __half g_a4h[(long long)MROWS*HH];
__device__ __half g_h2h[(long long)TT*BB*HH];

// ---------------- TMA 1D bulk + mbarrier helpers ----------------
__device__ __forceinline__ unsigned smaddr(const void* p) {
    return (unsigned)__cvta_generic_to_shared(p);
}
__device__ __forceinline__ void mbinit(unsigned mbar, unsigned cnt) {
    asm volatile("mbarrier.init.shared.b64 [%0], %1;" :: "r"(mbar), "r"(cnt) : "memory");
}
__device__ __forceinline__ void mexpect(unsigned mbar, unsigned bytes) {
    asm volatile("mbarrier.arrive.expect_tx.shared.b64 _, [%0], %1;"
                 :: "r"(mbar), "r"(bytes) : "memory");
}
__device__ __forceinline__ void mwait(unsigned mbar, unsigned parity) {
    asm volatile(
        "{\n\t.reg .pred P;\n\t"
        "LW%=:\n\t"
        "mbarrier.try_wait.parity.acquire.cta.shared::cta.b64 P, [%0], %1, 0x989680;\n\t"
        "@P bra LD%=;\n\t"
        "bra LW%=;\n\t"
        "LD%=:\n\t}"
        :: "r"(mbar), "r"(parity) : "memory");
}
__device__ __forceinline__ void bulkcp(unsigned dst, const void* src, unsigned bytes, unsigned mbar) {
    asm volatile(
        "cp.async.bulk.shared::cluster.global.mbarrier::complete_tx::bytes [%0], [%1], %2, [%3];"
        :: "r"(dst), "l"(src), "r"(bytes), "r"(mbar) : "memory");
}

__global__ void k0_setup(const int* __restrict__ caps, const int* __restrict__ lens,
                         float* __restrict__ out, long long out_size) {
    __shared__ int cnt[TT], off[TT+1];
    int t = threadIdx.x;
    if (t == 0) {
        g_bar = 0u;
        int len[BB]; bool used[BB];
        for (int i = 0; i < BB; i++) { len[i] = lens[i]; used[i] = false; }
        for (int r = 0; r < BB; r++) {
            int best = -1;
            for (int i = 0; i < BB; i++)
                if (!used[i] && (best < 0 || len[i] > len[best])) best = i;
            used[best] = true; g_sort[r] = best; g_declen[r] = len[best] - 1;
        }
    }
    __syncthreads();
    if (t < TT) {
        int c = 0;
        for (int b = 0; b < BB; b++) if (g_declen[b] > t) c++;
        cnt[t] = c;
    }
    __syncthreads();
    if (t == 0) {
        int s = 0;
        for (int i = 0; i < TT; i++) { off[i] = s; s += cnt[i]; }
        off[TT] = s; g_mact = s;
    }
    __syncthreads();
    for (int i = t; i < TT*BB; i += blockDim.x) {
        int tt = i >> 5, bb = i & 31;
        if (g_declen[bb] > tt) g_prow[off[tt] + bb] = i;
    }
    long long P = (long long)BB * TT * VV;
    for (int i = t; i < BB*LL; i += blockDim.x) {
        int b = i / LL, c = i % LL;
        int v = caps[g_sort[b]*LL + c];
        g_caps[i] = v;
        if (P + i < out_size) out[P + i] = (float)v;
    }
    for (int i = t; i < BB; i += blockDim.x) {
        if (P + BB*LL + i      < out_size) out[P + BB*LL + i]      = (float)g_declen[i];
        if (P + BB*LL + BB + i < out_size) out[P + BB*LL + BB + i] = (float)g_sort[i];
    }
}

// zero-fill inactive prediction rows (also keeps k1 at ncu profile slot 3)
__global__ void kzero(float* __restrict__ out, long long out_size) {
    int bid = blockIdx.x;
    int tt = bid >> 5, bb = bid & 31;
    if (g_declen[bb] > tt) return;
    long long base = (long long)bb * TT * VV + (long long)tt * VV;
    for (int i = threadIdx.x; i < VV; i += blockDim.x) {
        long long idx = base + i;
        if (idx < out_size) out[idx] = 0.f;
    }
}

// convert wih + fcw to half (grid-stride)
__global__ void kc_w(const float* __restrict__ wih, const float* __restrict__ fcw) {
    const long long NW = (long long)G4 * HH;
    const long long NF = (long long)VV * HH;
    long long i = (long long)blockIdx.x * blockDim.x + threadIdx.x;
    long long stride = (long long)gridDim.x * blockDim.x;
    for (; i < NW + NF; i += stride) {
        if (i < NW) g_wih_h[i] = __float2half(wih[i]);
        else        g_fcw_h[i - NW] = __float2half(fcw[i - NW]);
    }
}

// build A-half for k4
__global__ void kc_a4(const float* __restrict__ embw) {
    int r = blockIdx.x, t = threadIdx.x;
    const float* src;
    if (r < BB) src = g_x0bn + r * HH;
    else { int rr = r - BB; src = embw + (long long)g_caps[(rr & 31)*LL + (rr >> 5)] * HH; }
    __half* dst = g_a4h + (long long)r * HH;
    for (int i = t; i < HH; i += blockDim.x) dst[i] = __float2half(src[i]);
}

// ---- k1: x0 partials. TMA stages fp32 (K=128), in-smem cvt to fp16, fp16 wmma.
// Tile 32m x 64n, grid (8, 32). 8 warps = 4 n-warps x 2 k-warps (K=64 halves each).
__global__ __launch_bounds__(256) void k1_initgemm(const float* __restrict__ enc,
                                                   const float* __restrict__ w) {
    extern __shared__ float sm[];
    __shared__ unsigned long long mb[2];
    const int SST = 96 * 132;                 // fp32 stage stride (floats)
    __half* smh = (__half*)(sm + 2 * SST);    // fp16 compute buffer: 96 rows x 136 halves
    int t = threadIdx.x;
    int wid = t >> 5, wk = wid >> 2, wn = wid & 3;
    int n0 = blockIdx.x * 64;
    long long kbase = (long long)blockIdx.y * KCHUNK;
    unsigned mbar[2] = { smaddr(&mb[0]), smaddr(&mb[1]) };
    if (t == 0) { mbinit(mbar[0], 1); mbinit(mbar[1], 1); }
    __syncthreads();

    const int STAGES = KCHUNK / 128;          // 98
    const unsigned STB = 96u * 512u;          // 49152 B/stage

    // copy role: t<32 -> enc row t (smem rows 0..31); t in [32,96) -> w row n0+t-32
    const float* src0 = 0;
    int drow = 0;
    if (t < 32)      { src0 = enc + (long long)g_sort[t] * ENCK + kbase;   drow = t * 132; }
    else if (t < 96) { src0 = w + (long long)(n0 + t - 32) * ENCK + kbase; drow = t * 132; }

    wmma::fragment<wmma::accumulator,16,16,16,float> acc[2];
    wmma::fill_fragment(acc[0], 0.f);
    wmma::fill_fragment(acc[1], 0.f);

    if (t == 0) mexpect(mbar[0], STB);
    __syncthreads();
    if (t < 96) bulkcp(smaddr(sm + drow), src0, 512, mbar[0]);
    if (t == 0) mexpect(mbar[1], STB);
    __syncthreads();
    if (t < 96) bulkcp(smaddr(sm + SST + drow), src0 + 128, 512, mbar[1]);

    for (int s = 0; s < STAGES; s++) {
        int c = s & 1;
        mwait(mbar[c], (unsigned)((s >> 1) & 1));
        __syncthreads();   // all warps done reading smh from previous stage
        {   // convert fp32 stage -> fp16 buffer (12 float4 per thread)
            const float* S = sm + c * SST;
#pragma unroll
            for (int i = 0; i < 12; i++) {
                int idx = t + i*256;          // 0..3071 over 96 rows x 32 float4
                int row = idx >> 5, q = idx & 31;
                float4 v = *(const float4*)&S[row*132 + q*4];
                *(__half2*)&smh[row*136 + q*4]     = __floats2half2_rn(v.x, v.y);
                *(__half2*)&smh[row*136 + q*4 + 2] = __floats2half2_rn(v.z, v.w);
            }
        }
        __syncthreads();   // conversion visible; fp32 buffer c now free
        if (s + 2 < STAGES) {
            if (t == 0) mexpect(mbar[c], STB);
            __syncthreads();
            if (t < 96) bulkcp(smaddr(sm + c*SST + drow), src0 + (long long)(s+2)*128, 512, mbar[c]);
        }
        {   // fp16 compute: k-warp wk covers halves [wk*64, wk*64+64)
            __half* Ah = smh;
            __half* Bh = smh + 32 * 136;
            int kofs = wk * 64;
#pragma unroll
            for (int ks = 0; ks < 4; ks++) {
                wmma::fragment<wmma::matrix_a,16,16,16,__half,wmma::row_major> af[2];
                wmma::fragment<wmma::matrix_b,16,16,16,__half,wmma::col_major> bf;
#pragma unroll
                for (int mi = 0; mi < 2; mi++)
                    wmma::load_matrix_sync(af[mi], &Ah[(mi*16)*136 + kofs + ks*16], 136);
                wmma::load_matrix_sync(bf, &Bh[(wn*16)*136 + kofs + ks*16], 136);
                wmma::mma_sync(acc[0], af[0], bf, acc[0]);
                wmma::mma_sync(acc[1], af[1], bf, acc[1]);
            }
        }
    }
    __syncthreads();
    // reduce 2 k-warp partials via smem (reuse fp32 buffers; ld 68, %4==0)
    float* sP = sm;    // [wk][32][68]
#pragma unroll
    for (int mi = 0; mi < 2; mi++)
        wmma::store_matrix_sync(&sP[wk*2176 + (mi*16)*68 + wn*16], acc[mi], 68, wmma::mem_row_major);
    __syncthreads();
    float* base = g_part + (long long)blockIdx.y * BB * HH;
#pragma unroll
    for (int i = 0; i < 8; i++) {
        int idx = t + i*256;
        int row = idx >> 6, col = idx & 63;
        base[row*HH + n0 + col] = sP[row*68 + col] + sP[2176 + row*68 + col];
    }
}

__global__ void k2_bn(const float* __restrict__ bias, const float* __restrict__ gamma,
                      const float* __restrict__ beta) {
    int n = blockIdx.x, t = threadIdx.x;
    int b = t & 31, grp = t >> 5;
    float s = 0.f;
    for (int ks = grp; ks < KSPLIT; ks += 4)
        s += g_part[((long long)ks * BB + b) * HH + n];
    __shared__ float red[128];
    red[t] = s; __syncthreads();
    if (t < 32) {
        float x = red[t] + red[t+32] + red[t+64] + red[t+96] + bias[n];
        float sum = x, sq = x * x;
#pragma unroll
        for (int o = 16; o > 0; o >>= 1) {
            sum += __shfl_xor_sync(0xffffffffu, sum, o);
            sq  += __shfl_xor_sync(0xffffffffu, sq,  o);
        }
        float mu = sum * (1.f/32.f);
        float var = sq * (1.f/32.f) - mu * mu;
        g_x0bn[b * HH + n] = (x - mu) * rsqrtf(var + 1e-5f) * gamma[n] + beta[n];
    }
}

// ---- fp16 bulk-TMA GEMM body: tile 128m x 256n, K=512, stage K=128 halves.
template<typename EPI>
__device__ __forceinline__ void bulk_gemm_h(const __half* arow0, const __half* brow0,
                                            __half* smh, EPI epi) {
    __shared__ unsigned long long mb[2];
    int t = threadIdx.x;
    int wid = t >> 5, wm = wid >> 2, wn = wid & 3;
    unsigned mbar[2] = { smaddr(&mb[0]), smaddr(&mb[1]) };
    if (t == 0) { mbinit(mbar[0], 1); mbinit(mbar[1], 1); }
    __syncthreads();

    const int STAGES = HH / 128;            // 4
    const unsigned STB = 384u * 256u;
    const int SST = 384 * 136;
    int adrow = t * 136;
    int bdrow = (128 + t) * 136;

    wmma::fragment<wmma::accumulator,16,16,16,float> acc[4][4];
#pragma unroll
    for (int mi = 0; mi < 4; mi++)
#pragma unroll
        for (int nj = 0; nj < 4; nj++) wmma::fill_fragment(acc[mi][nj], 0.f);

    if (t == 0) mexpect(mbar[0], STB);
    __syncthreads();
    bulkcp(smaddr(smh + bdrow), brow0, 256, mbar[0]);
    if (t < 128) bulkcp(smaddr(smh + adrow), arow0, 256, mbar[0]);
    if (t == 0) mexpect(mbar[1], STB);
    __syncthreads();
    bulkcp(smaddr(smh + SST + bdrow), brow0 + 128, 256, mbar[1]);
    if (t < 128) bulkcp(smaddr(smh + SST + adrow), arow0 + 128, 256, mbar[1]);

    for (int s = 0; s < STAGES; s++) {
        int c = s & 1;
        mwait(mbar[c], (unsigned)((s >> 1) & 1));
        __half* As = smh + c * SST;
        __half* Bs = As + 128 * 136;
#pragma unroll
        for (int ks = 0; ks < 8; ks++) {
            wmma::fragment<wmma::matrix_a,16,16,16,__half,wmma::row_major> af[4];
            wmma::fragment<wmma::matrix_b,16,16,16,__half,wmma::col_major> bf[4];
#pragma unroll
            for (int mi = 0; mi < 4; mi++)
                wmma::load_matrix_sync(af[mi], &As[(wm*64 + mi*16)*136 + ks*16], 136);
#pragma unroll
            for (int nj = 0; nj < 4; nj++)
                wmma::load_matrix_sync(bf[nj], &Bs[(wn*64 + nj*16)*136 + ks*16], 136);
#pragma unroll
            for (int mi = 0; mi < 4; mi++)
#pragma unroll
                for (int nj = 0; nj < 4; nj++)
                    wmma::mma_sync(acc[mi][nj], af[mi], bf[nj], acc[mi][nj]);
        }
        __syncthreads();
        if (s + 2 < STAGES) {
            if (t == 0) mexpect(mbar[c], STB);
            __syncthreads();
            bulkcp(smaddr(smh + c*SST + bdrow), brow0 + (s+2)*128, 256, mbar[c]);
            if (t < 128) bulkcp(smaddr(smh + c*SST + adrow), arow0 + (s+2)*128, 256, mbar[c]);
        }
    }
    float* sC = (float*)smh;
#pragma unroll
    for (int mi = 0; mi < 4; mi++)
#pragma unroll
        for (int nj = 0; nj < 4; nj++)
            wmma::store_matrix_sync(&sC[(wm*64 + mi*16)*260 + wn*64 + nj*16],
                                    acc[mi][nj], 260, wmma::mem_row_major);
    __syncthreads();
    epi(sC);
}

// ---- k4: XW = A4h(1664x512) @ wih_h.T + bias. grid (13, 8).
__global__ __launch_bounds__(256) void k4_xw(const float* __restrict__ bih,
                                             const float* __restrict__ bhh) {
    extern __shared__ __half sm4[];
    int t = threadIdx.x;
    int m0 = blockIdx.x * 128, n0 = blockIdx.y * 256;
    const __half* arow0 = (t < 128) ? g_a4h + (long long)(m0 + t) * HH : 0;
    const __half* brow0 = g_wih_h + (long long)(n0 + t) * HH;
    bulk_gemm_h(arow0, brow0, sm4, [&](float* sC) {
#pragma unroll
        for (int j = 0; j < 128; j++) {
            int e = t + j*256;
            int row = e >> 8, cl = e & 255;
            int col = n0 + cl;
            g_xw[(long long)(m0 + row) * G4 + col] = sC[row*260 + cl] + bih[col] + bhh[col];
        }
    });
}

// ---- k5: persistent LSTM via fp16 wmma. 32 blocks x 128 thr.
__global__ __launch_bounds__(128) void k5_all(const float* __restrict__ whh) {
    extern __shared__ __half smh5[];
    __half* Bs = smh5;                      // [64][520]
    __half* Ah = smh5 + 64*520;             // [32][520]
    float*  sP = (float*)(smh5 + 96*520);   // [4][32][PLD]
    int t = threadIdx.x;
    int w = t >> 5;
    int c0 = blockIdx.x * 16;

    {   // convert whh slice to fp16 smem once
        int r = t >> 1, g = r >> 4, j = r & 15;
        const float* wp = whh + (long long)(g*512 + c0 + j) * HH + (t & 1) * 256;
        __half* dst = Bs + r*520 + (t & 1) * 256;
#pragma unroll 8
        for (int i = 0; i < 64; i++) {
            float4 v = *(const float4*)(wp + i*4);
            *(__half2*)(dst + i*4)     = __floats2half2_rn(v.x, v.y);
            *(__half2*)(dst + i*4 + 2) = __floats2half2_rn(v.z, v.w);
        }
    }
    {
        unsigned* az = (unsigned*)Ah;
        for (int i = t; i < 32*520/2; i += 128) az[i] = 0u;
    }

    int eb = t & 31;
    float c_reg[4] = {0.f,0.f,0.f,0.f}, h_reg[4] = {0.f,0.f,0.f,0.f};
    int dl = g_declen[eb];
    int hb = t >> 2, hq = (t & 3) * 128;

    for (int cell = 0; cell < LL; cell++) {
        if (cell > 0) {
            const float* hp = g_hbuf[cell & 1] + hb * HH + hq;
            __half* dst = Ah + hb*520 + hq;
#pragma unroll 8
            for (int i = 0; i < 32; i++) {
                float4 v = __ldcg((const float4*)(hp + i*4));
                *(__half2*)(dst + i*4)     = __floats2half2_rn(v.x, v.y);
                *(__half2*)(dst + i*4 + 2) = __floats2half2_rn(v.z, v.w);
            }
        }
        __syncthreads();
        {
            wmma::fragment<wmma::accumulator,16,16,16,float> acc[2][4];
#pragma unroll
            for (int mi = 0; mi < 2; mi++)
#pragma unroll
                for (int nj = 0; nj < 4; nj++) wmma::fill_fragment(acc[mi][nj], 0.f);
            int kw = w * 128;
#pragma unroll
            for (int ks = 0; ks < 8; ks++) {
                wmma::fragment<wmma::matrix_a,16,16,16,__half,wmma::row_major> af[2];
                wmma::fragment<wmma::matrix_b,16,16,16,__half,wmma::col_major> bf[4];
#pragma unroll
                for (int mi = 0; mi < 2; mi++)
                    wmma::load_matrix_sync(af[mi], &Ah[(mi*16)*520 + kw + ks*16], 520);
#pragma unroll
                for (int nj = 0; nj < 4; nj++)
                    wmma::load_matrix_sync(bf[nj], &Bs[(nj*16)*520 + kw + ks*16], 520);
#pragma unroll
                for (int mi = 0; mi < 2; mi++)
#pragma unroll
                    for (int nj = 0; nj < 4; nj++)
                        wmma::mma_sync(acc[mi][nj], af[mi], bf[nj], acc[mi][nj]);
            }
            float* sPw = sP + w * 32 * PLD;
#pragma unroll
            for (int mi = 0; mi < 2; mi++)
#pragma unroll
                for (int nj = 0; nj < 4; nj++)
                    wmma::store_matrix_sync(&sPw[(mi*16)*PLD + nj*16],
                                            acc[mi][nj], PLD, wmma::mem_row_major);
        }
        __syncthreads();
        {
            const float* xw = g_xw + ((long long)cell * BB + eb) * G4;
#pragma unroll
            for (int jj = 0; jj < 4; jj++) {
                int j = w * 4 + jj;
                int col = c0 + j;
                float gv4[4];
#pragma unroll
                for (int g = 0; g < 4; g++) {
                    int n = g * 16 + j;
                    float s = sP[0*32*PLD + eb*PLD + n] + sP[1*32*PLD + eb*PLD + n]
                            + sP[2*32*PLD + eb*PLD + n] + sP[3*32*PLD + eb*PLD + n];
                    gv4[g] = s + xw[g*512 + col];
                }
                float si = 1.f/(1.f+expf(-gv4[0])), sf = 1.f/(1.f+expf(-gv4[1]));
                float tg = tanhf(gv4[2]),           so = 1.f/(1.f+expf(-gv4[3]));
                float cn = sf * c_reg[jj] + si * tg;
                float hn = so * tanhf(cn);
                bool act = (cell == 0) || (dl > (cell - 1));
                c_reg[jj] = act ? cn : c_reg[jj];
                h_reg[jj] = act ? hn : h_reg[jj];
                g_hbuf[(cell + 1) & 1][eb * HH + col] = h_reg[jj];
                if (cell >= 1)
                    g_h2h[((long long)(cell - 1) * BB + eb) * HH + col] = __float2half(hn);
            }
        }
        __syncthreads();
        if (cell + 1 < LL) {
            if (t == 0) {
                __threadfence();
                atomicAdd(&g_bar, 1u);
                unsigned tgt = (unsigned)(cell + 1) * gridDim.x;
                while (*(volatile unsigned*)&g_bar < tgt) __nanosleep(64);
            }
            __syncthreads();
        }
    }
}

// ---- k6: packed-M predictions. grid (13, 40); blocks beyond g_mact exit.
__global__ __launch_bounds__(256) void k6_fc(const float* __restrict__ fcb,
                                             float* __restrict__ out, long long out_size) {
    extern __shared__ __half sm6[];
    int t = threadIdx.x;
    int m0 = blockIdx.x * 128, n0 = blockIdx.y * 256;
    int Mact = g_mact;
    if (m0 >= Mact) return;
    const __half* arow0 = 0;
    if (t < 128) {
        int p = m0 + t;
        if (p >= Mact) p = 0;
        arow0 = g_h2h + (long long)g_prow[p] * HH;
    }
    int bn = n0 + t; if (bn >= VV) bn = VV - 1;
    const __half* brow0 = g_fcw_h + (long long)bn * HH;
    bulk_gemm_h(arow0, brow0, sm6, [&](float* sC) {
#pragma unroll
        for (int j = 0; j < 128; j++) {
            int e = t + j*256;
            int row = e >> 8, cl = e & 255;
            int p = m0 + row;
            if (p >= Mact) continue;
            int col = n0 + cl;
            if (col >= VV) continue;
            int rr = g_prow[p];
            int tt = rr >> 5, bb = rr & 31;
            long long idx = (long long)bb * TT * VV + (long long)tt * VV + col;
            if (idx < out_size)
                out[idx] = sC[row*260 + cl] + fcb[col];
        }
    });
}

extern "C" void kernel_launch(void* const* d_in, const int* in_sizes, int n_in,
                              void* d_out, int out_size) {
    const float* enc   = (const float*)d_in[0];
    const int*   caps  = (const int*)  d_in[1];
    const int*   lens  = (const int*)  d_in[2];
    const float* embw  = (const float*)d_in[3];
    const float* initw = (const float*)d_in[4];
    const float* initb = (const float*)d_in[5];
    const float* gamma = (const float*)d_in[6];
    const float* beta  = (const float*)d_in[7];
    const float* wih   = (const float*)d_in[8];
    const float* whh   = (const float*)d_in[9];
    const float* bih   = (const float*)d_in[10];
    const float* bhh   = (const float*)d_in[11];
    const float* fcw   = (const float*)d_in[12];
    const float* fcb   = (const float*)d_in[13];
    float* out = (float*)d_out;
    long long osz = (long long)out_size;

    const int SM1  = 2*96*132*4 + 96*136*2;     // 101,376 + 26,112 = 127,488 B
    const int SMGH = 2 * 384 * 136 * 2;         // 208,896 B
    const int SM5  = 96*520*2 + 4*32*PLD*4;     // 136,704 B
    cudaFuncSetAttribute(k1_initgemm, cudaFuncAttributeMaxDynamicSharedMemorySize, SM1);
    cudaFuncSetAttribute(k4_xw,       cudaFuncAttributeMaxDynamicSharedMemorySize, SMGH);
    cudaFuncSetAttribute(k6_fc,       cudaFuncAttributeMaxDynamicSharedMemorySize, SMGH);
    cudaFuncSetAttribute(k5_all,      cudaFuncAttributeMaxDynamicSharedMemorySize, SM5);

    k0_setup<<<1, 256>>>(caps, lens, out, osz);
    kzero<<<TT*BB, 256>>>(out, osz);
    kc_w<<<592, 256>>>(wih, fcw);
    k1_initgemm<<<dim3(8, KSPLIT), 256, SM1>>>(enc, initw);   // profile slot 3
    k2_bn<<<512, 128>>>(initb, gamma, beta);
    kc_a4<<<MROWS, 128>>>(embw);
    k4_xw<<<dim3(13, 8), 256, SMGH>>>(bih, bhh);
    k5_all<<<32, 128, SM5>>>(whh);
    k6_fc<<<dim3(13, 40), 256, SMGH>>>(fcb, out, osz);
}